// round 9
// baseline (speedup 1.0000x reference)
#include <cuda_runtime.h>

#define BATCH 4
#define SEQ   2048
#define HID   1024
#define NHEAD 16
#define HDIM  64

typedef unsigned long long u64;

// Scratch (static device globals — allowed; no runtime allocation)
__device__ float g_q[BATCH*NHEAD*SEQ*HDIM];
__device__ float g_k[BATCH*NHEAD*SEQ*HDIM];
__device__ float g_v[BATCH*NHEAD*SEQ*HDIM];
__device__ float g_attn[BATCH*SEQ*HID];

// ---------------------------------------------------------------------------
// packed f32x2 helpers (exact fp32 semantics: two independent FMAs per op)
// ---------------------------------------------------------------------------
__device__ __forceinline__ u64 pk2(float lo, float hi) {
    u64 r;
    asm("mov.b64 %0, {%1, %2};" : "=l"(r) : "f"(lo), "f"(hi));
    return r;
}
__device__ __forceinline__ float2 upk2(u64 v) {
    float2 f;
    asm("mov.b64 {%0, %1}, %2;" : "=f"(f.x), "=f"(f.y) : "l"(v));
    return f;
}
__device__ __forceinline__ u64 ffma2(u64 a, u64 b, u64 c) {
    u64 d;
    asm("fma.rn.f32x2 %0, %1, %2, %3;" : "=l"(d) : "l"(a), "l"(b), "l"(c));
    return d;
}

// ---------------------------------------------------------------------------
// Stage 1: QKV GEMM  C[m][n] = x[m][:] . w_qkv[:][n] + b_qkv[n]
// Identical structure to R8 (register-staged prefetch, same tiles/barriers);
// only the inner product is packed f32x2 (accumulators paired along n).
// ---------------------------------------------------------------------------
__global__ __launch_bounds__(256) void qkv_gemm(const float* __restrict__ A,
                                                const float* __restrict__ W,
                                                const float* __restrict__ bias)
{
    const int K = HID;
    const int N = 3 * HID;
    __shared__ float As[8][128];
    __shared__ float Bs[8][128];

    const int tid = threadIdx.x;
    const int m0 = blockIdx.y * 128;
    const int n0 = blockIdx.x * 128;

    const int arow = tid >> 1;          // 0..127
    const int acol = (tid & 1) * 4;     // 0 or 4
    const int brow = tid >> 5;          // 0..7
    const int bcol = (tid & 31) * 4;    // 0..124

    const float* Ap = A + (m0 + arow) * K + acol;
    const float* Bp = W + brow * N + n0 + bcol;

    u64 accp[8][4];
    #pragma unroll
    for (int i = 0; i < 8; i++)
        #pragma unroll
        for (int j = 0; j < 4; j++) accp[i][j] = 0ull;

    const int ty = tid >> 4, tx = tid & 15;

    // stage tile 0
    float4 av = *(const float4*)(Ap);
    float4 bv = *(const float4*)(Bp);

    for (int k0 = 0; k0 < K; k0 += 8) {
        As[acol + 0][arow] = av.x;
        As[acol + 1][arow] = av.y;
        As[acol + 2][arow] = av.z;
        As[acol + 3][arow] = av.w;
        *(float4*)&Bs[brow][bcol] = bv;
        __syncthreads();

        // issue next tile's loads now; latency overlaps the compute below
        if (k0 + 8 < K) {
            av = *(const float4*)(Ap + k0 + 8);
            bv = *(const float4*)(Bp + (long)(k0 + 8) * N);
        }

        #pragma unroll
        for (int kk = 0; kk < 8; kk++) {
            float4 a0 = *(const float4*)&As[kk][ty * 8];
            float4 a1 = *(const float4*)&As[kk][ty * 8 + 4];
            float4 b0 = *(const float4*)&Bs[kk][tx * 8];
            float4 b1 = *(const float4*)&Bs[kk][tx * 8 + 4];
            u64 ap[8] = { pk2(a0.x,a0.x), pk2(a0.y,a0.y), pk2(a0.z,a0.z), pk2(a0.w,a0.w),
                          pk2(a1.x,a1.x), pk2(a1.y,a1.y), pk2(a1.z,a1.z), pk2(a1.w,a1.w) };
            u64 bp[4] = { pk2(b0.x,b0.y), pk2(b0.z,b0.w),
                          pk2(b1.x,b1.y), pk2(b1.z,b1.w) };
            #pragma unroll
            for (int i = 0; i < 8; i++)
                #pragma unroll
                for (int j = 0; j < 4; j++)
                    accp[i][j] = ffma2(ap[i], bp[j], accp[i][j]);
        }
        __syncthreads();
    }

    // Epilogue: scatter to Q/K/V head-major layouts, add bias (R8 logic,
    // scalar stores; pairs unpacked).
    #pragma unroll
    for (int i = 0; i < 8; i++) {
        const int m = m0 + ty * 8 + i;
        const int bb = m >> 11;          // / SEQ
        const int s  = m & 2047;
        #pragma unroll
        for (int j2 = 0; j2 < 4; j2++) {
            float2 f = upk2(accp[i][j2]);
            #pragma unroll
            for (int u = 0; u < 2; u++) {
                const int n = n0 + tx * 8 + 2 * j2 + u;
                const float v = (u ? f.y : f.x) + bias[n];
                const int which = n >> 10;
                const int rem = n & 1023;
                const int h = rem >> 6;
                const int d = rem & 63;
                const int idx = (((bb * NHEAD) + h) * SEQ + s) * HDIM + d;
                if (which == 0)      g_q[idx] = v;
                else if (which == 1) g_k[idx] = v;
                else                 g_v[idx] = v;
            }
        }
    }
}

// ---------------------------------------------------------------------------
// Stage 2: causal flash attention, fp32.
// Byte-identical to the R8 passing version.
// ---------------------------------------------------------------------------
__global__ __launch_bounds__(256) void flash_attn()
{
    extern __shared__ float sm[];
    float (*Qs)[65]  = (float(*)[65])sm;
    float (*KPs)[65] = (float(*)[65])(sm + 64 * 65);
    float (*Vs)[65]  = (float(*)[65])(sm + 2 * 64 * 65);

    const int b  = blockIdx.z;
    const int h  = blockIdx.y;
    const int qt = blockIdx.x;
    const int q0 = qt * 64;

    const float* Qg  = g_q + (((long)(b * NHEAD + h)) * SEQ + q0) * HDIM;
    const float* Kg0 = g_k + ((long)(b * NHEAD + h)) * SEQ * HDIM;
    const float* Vg0 = g_v + ((long)(b * NHEAD + h)) * SEQ * HDIM;

    const int tid = threadIdx.x;
    const int ty = tid >> 4, tx = tid & 15;

    // load Q tile
    for (int i = tid; i < 64 * 64; i += 256) {
        Qs[i >> 6][i & 63] = Qg[i];
    }

    float m_i[4], l_i[4], acc[4][4];
    #pragma unroll
    for (int i = 0; i < 4; i++) {
        m_i[i] = -1e30f;
        l_i[i] = 0.0f;
        #pragma unroll
        for (int j = 0; j < 4; j++) acc[i][j] = 0.0f;
    }

    const float scale = 0.125f; // HD^-0.5
    const int ntiles = qt + 1;

    for (int t = 0; t < ntiles; t++) {
        const int k0 = t * 64;
        __syncthreads();   // prior PV reads done (and Q load at t=0)
        for (int i = tid; i < 64 * 64; i += 256) {
            const int r = i >> 6, c = i & 63;
            KPs[r][c] = Kg0[k0 * HDIM + i];
            Vs[r][c]  = Vg0[k0 * HDIM + i];
        }
        __syncthreads();

        // S = Q K^T   (4x4 per thread)
        float s[4][4] = {};
        #pragma unroll 4
        for (int d = 0; d < 64; d++) {
            float qv[4], kv[4];
            #pragma unroll
            for (int i = 0; i < 4; i++) qv[i] = Qs[4 * ty + i][d];
            #pragma unroll
            for (int j = 0; j < 4; j++) kv[j] = KPs[4 * tx + j][d];
            #pragma unroll
            for (int i = 0; i < 4; i++)
                #pragma unroll
                for (int j = 0; j < 4; j++)
                    s[i][j] += qv[i] * kv[j];
        }

        // scale + causal mask
        #pragma unroll
        for (int i = 0; i < 4; i++) {
            const int rg = q0 + 4 * ty + i;
            #pragma unroll
            for (int j = 0; j < 4; j++) {
                const int cg = k0 + 4 * tx + j;
                float val = s[i][j] * scale;
                if (cg > rg) val = -1e30f;
                s[i][j] = val;
            }
        }

        // online softmax (row reductions across 16-lane tx groups)
        #pragma unroll
        for (int i = 0; i < 4; i++) {
            float mx = fmaxf(fmaxf(s[i][0], s[i][1]), fmaxf(s[i][2], s[i][3]));
            #pragma unroll
            for (int off = 8; off >= 1; off >>= 1)
                mx = fmaxf(mx, __shfl_xor_sync(0xffffffffu, mx, off));
            const float mn = fmaxf(m_i[i], mx);
            const float corr = __expf(m_i[i] - mn);
            m_i[i] = mn;
            float rs = 0.0f;
            #pragma unroll
            for (int j = 0; j < 4; j++) {
                s[i][j] = __expf(s[i][j] - mn);
                rs += s[i][j];
            }
            #pragma unroll
            for (int off = 8; off >= 1; off >>= 1)
                rs += __shfl_xor_sync(0xffffffffu, rs, off);
            l_i[i] = l_i[i] * corr + rs;
            #pragma unroll
            for (int j = 0; j < 4; j++) acc[i][j] *= corr;
        }

        __syncthreads();   // everyone done reading K before overwriting as P
        #pragma unroll
        for (int i = 0; i < 4; i++)
            #pragma unroll
            for (int j = 0; j < 4; j++)
                KPs[4 * ty + i][4 * tx + j] = s[i][j];
        __syncthreads();

        // O += P V
        #pragma unroll 4
        for (int kk = 0; kk < 64; kk++) {
            float pv[4], vv[4];
            #pragma unroll
            for (int i = 0; i < 4; i++) pv[i] = KPs[4 * ty + i][kk];
            #pragma unroll
            for (int j = 0; j < 4; j++) vv[j] = Vs[kk][4 * tx + j];
            #pragma unroll
            for (int i = 0; i < 4; i++)
                #pragma unroll
                for (int j = 0; j < 4; j++)
                    acc[i][j] += pv[i] * vv[j];
        }
    }

    // write out: g_attn[b][s][h*HD + d]
    #pragma unroll
    for (int i = 0; i < 4; i++) {
        const int rg = q0 + 4 * ty + i;
        const float inv_l = 1.0f / l_i[i];
        #pragma unroll
        for (int j = 0; j < 4; j++) {
            g_attn[((long)(b * SEQ + rg)) * HID + h * HDIM + 4 * tx + j] =
                acc[i][j] * inv_l;
        }
    }
}

// ---------------------------------------------------------------------------
// Stage 3: output projection  out = attn @ w_out + b_out
// M=8192, K=1024, N=1024. Same structure as R8; packed f32x2 inner product.
// ---------------------------------------------------------------------------
__global__ __launch_bounds__(256) void out_gemm(const float* __restrict__ W,
                                                const float* __restrict__ bias,
                                                float* __restrict__ Out)
{
    const int K = HID;
    const int N = HID;
    __shared__ float As[8][128];
    __shared__ float Bs[8][128];

    const int tid = threadIdx.x;
    const int m0 = blockIdx.y * 128;
    const int n0 = blockIdx.x * 128;

    const int arow = tid >> 1;
    const int acol = (tid & 1) * 4;
    const int brow = tid >> 5;
    const int bcol = (tid & 31) * 4;

    const float* Ap = g_attn + (long)(m0 + arow) * K + acol;
    const float* Bp = W + brow * N + n0 + bcol;

    u64 accp[8][4];
    #pragma unroll
    for (int i = 0; i < 8; i++)
        #pragma unroll
        for (int j = 0; j < 4; j++) accp[i][j] = 0ull;

    const int ty = tid >> 4, tx = tid & 15;

    float4 av = *(const float4*)(Ap);
    float4 bv = *(const float4*)(Bp);

    for (int k0 = 0; k0 < K; k0 += 8) {
        As[acol + 0][arow] = av.x;
        As[acol + 1][arow] = av.y;
        As[acol + 2][arow] = av.z;
        As[acol + 3][arow] = av.w;
        *(float4*)&Bs[brow][bcol] = bv;
        __syncthreads();

        if (k0 + 8 < K) {
            av = *(const float4*)(Ap + k0 + 8);
            bv = *(const float4*)(Bp + (long)(k0 + 8) * N);
        }

        #pragma unroll
        for (int kk = 0; kk < 8; kk++) {
            float4 a0 = *(const float4*)&As[kk][ty * 8];
            float4 a1 = *(const float4*)&As[kk][ty * 8 + 4];
            float4 b0 = *(const float4*)&Bs[kk][tx * 8];
            float4 b1 = *(const float4*)&Bs[kk][tx * 8 + 4];
            u64 ap[8] = { pk2(a0.x,a0.x), pk2(a0.y,a0.y), pk2(a0.z,a0.z), pk2(a0.w,a0.w),
                          pk2(a1.x,a1.x), pk2(a1.y,a1.y), pk2(a1.z,a1.z), pk2(a1.w,a1.w) };
            u64 bp[4] = { pk2(b0.x,b0.y), pk2(b0.z,b0.w),
                          pk2(b1.x,b1.y), pk2(b1.z,b1.w) };
            #pragma unroll
            for (int i = 0; i < 8; i++)
                #pragma unroll
                for (int j = 0; j < 4; j++)
                    accp[i][j] = ffma2(ap[i], bp[j], accp[i][j]);
        }
        __syncthreads();
    }

    #pragma unroll
    for (int i = 0; i < 8; i++) {
        const int m = m0 + ty * 8 + i;
        #pragma unroll
        for (int j2 = 0; j2 < 4; j2++) {
            const int n = n0 + tx * 8 + 2 * j2;
            float2 f = upk2(accp[i][j2]);
            Out[(long)m * N + n    ] = f.x + bias[n];
            Out[(long)m * N + n + 1] = f.y + bias[n + 1];
        }
    }
}

// ---------------------------------------------------------------------------
extern "C" void kernel_launch(void* const* d_in, const int* in_sizes, int n_in,
                              void* d_out, int out_size)
{
    const float* x     = (const float*)d_in[0];
    const float* w_qkv = (const float*)d_in[1];
    const float* b_qkv = (const float*)d_in[2];
    const float* w_out = (const float*)d_in[3];
    const float* b_out = (const float*)d_in[4];
    float* out = (float*)d_out;

    // Stage 1: QKV projection + head scatter
    qkv_gemm<<<dim3(3 * HID / 128, (BATCH * SEQ) / 128), 256>>>(x, w_qkv, b_qkv);

    // Stage 2: causal flash attention
    const int shmem = 3 * 64 * 65 * (int)sizeof(float);  // 49920 B > 48KB default
    cudaFuncSetAttribute(flash_attn,
                         cudaFuncAttributeMaxDynamicSharedMemorySize, shmem);
    flash_attn<<<dim3(SEQ / 64, NHEAD, BATCH), 256, shmem>>>();

    // Stage 3: output projection
    out_gemm<<<dim3(HID / 128, (BATCH * SEQ) / 128), 256>>>(w_out, b_out, out);
}

// round 10
// speedup vs baseline: 1.0897x; 1.0897x over previous
#include <cuda_runtime.h>

#define BATCH 4
#define SEQ   2048
#define HID   1024
#define NHEAD 16
#define HDIM  64

// Scratch (static device globals — allowed; no runtime allocation)
__device__ float g_q[BATCH*NHEAD*SEQ*HDIM];
__device__ float g_k[BATCH*NHEAD*SEQ*HDIM];
__device__ float g_v[BATCH*NHEAD*SEQ*HDIM];
__device__ float g_attn[BATCH*SEQ*HID];

// ---------------------------------------------------------------------------
// Stage 1: QKV GEMM  (byte-identical to the R8 passing version)
// ---------------------------------------------------------------------------
__global__ __launch_bounds__(256) void qkv_gemm(const float* __restrict__ A,
                                                const float* __restrict__ W,
                                                const float* __restrict__ bias)
{
    const int K = HID;
    const int N = 3 * HID;
    __shared__ float As[8][128];
    __shared__ float Bs[8][128];

    const int tid = threadIdx.x;
    const int m0 = blockIdx.y * 128;
    const int n0 = blockIdx.x * 128;

    const int arow = tid >> 1;          // 0..127
    const int acol = (tid & 1) * 4;     // 0 or 4
    const int brow = tid >> 5;          // 0..7
    const int bcol = (tid & 31) * 4;    // 0..124

    const float* Ap = A + (m0 + arow) * K + acol;
    const float* Bp = W + brow * N + n0 + bcol;

    float acc[8][8] = {};
    const int ty = tid >> 4, tx = tid & 15;

    // stage tile 0
    float4 av = *(const float4*)(Ap);
    float4 bv = *(const float4*)(Bp);

    for (int k0 = 0; k0 < K; k0 += 8) {
        As[acol + 0][arow] = av.x;
        As[acol + 1][arow] = av.y;
        As[acol + 2][arow] = av.z;
        As[acol + 3][arow] = av.w;
        *(float4*)&Bs[brow][bcol] = bv;
        __syncthreads();

        if (k0 + 8 < K) {
            av = *(const float4*)(Ap + k0 + 8);
            bv = *(const float4*)(Bp + (long)(k0 + 8) * N);
        }

        #pragma unroll
        for (int kk = 0; kk < 8; kk++) {
            float4 a0 = *(const float4*)&As[kk][ty * 8];
            float4 a1 = *(const float4*)&As[kk][ty * 8 + 4];
            float4 b0 = *(const float4*)&Bs[kk][tx * 8];
            float4 b1 = *(const float4*)&Bs[kk][tx * 8 + 4];
            float a[8] = {a0.x,a0.y,a0.z,a0.w,a1.x,a1.y,a1.z,a1.w};
            float b[8] = {b0.x,b0.y,b0.z,b0.w,b1.x,b1.y,b1.z,b1.w};
            #pragma unroll
            for (int i = 0; i < 8; i++)
                #pragma unroll
                for (int j = 0; j < 8; j++)
                    acc[i][j] += a[i] * b[j];
        }
        __syncthreads();
    }

    #pragma unroll
    for (int i = 0; i < 8; i++) {
        const int m = m0 + ty * 8 + i;
        const int bb = m >> 11;          // / SEQ
        const int s  = m & 2047;
        #pragma unroll
        for (int j = 0; j < 8; j++) {
            const int n = n0 + tx * 8 + j;
            const float v = acc[i][j] + bias[n];
            const int which = n >> 10;
            const int rem = n & 1023;
            const int h = rem >> 6;
            const int d = rem & 63;
            const int idx = (((bb * NHEAD) + h) * SEQ + s) * HDIM + d;
            if (which == 0)      g_q[idx] = v;
            else if (which == 1) g_k[idx] = v;
            else                 g_v[idx] = v;
        }
    }
}

// ---------------------------------------------------------------------------
// Stage 2: causal flash attention, fp32, vectorized-smem version.
// Q and K stored TRANSPOSED in smem ([d][row], pad 68) so the S-loop is
// 2 conflict-free LDS.128 + 16 FMA per d. V row-major (pad 68) so PV reads
// a float4 per kk. P row-major (broadcast pv reads). Identical arithmetic
// order to the R8 version (d-sequential, kk-sequential).
// Dynamic smem: 4 * 64*68 floats = 69632 B.
// ---------------------------------------------------------------------------
__global__ __launch_bounds__(256) void flash_attn()
{
    extern __shared__ float sm[];
    float (*QsT)[68] = (float(*)[68])sm;                  // [d][query]
    float (*KsT)[68] = (float(*)[68])(sm + 64 * 68);      // [d][key]
    float (*Vs)[68]  = (float(*)[68])(sm + 2 * 64 * 68);  // [key][d]
    float (*Ps)[68]  = (float(*)[68])(sm + 3 * 64 * 68);  // [query][key]

    const int b  = blockIdx.z;
    const int h  = blockIdx.y;
    const int qt = blockIdx.x;
    const int q0 = qt * 64;

    const float* Qg  = g_q + (((long)(b * NHEAD + h)) * SEQ + q0) * HDIM;
    const float* Kg0 = g_k + ((long)(b * NHEAD + h)) * SEQ * HDIM;
    const float* Vg0 = g_v + ((long)(b * NHEAD + h)) * SEQ * HDIM;

    const int tid = threadIdx.x;
    const int ty = tid >> 4, tx = tid & 15;

    // load Q tile transposed: QsT[d][q] = Q[q][d] (coalesced LDG)
    for (int i = tid; i < 64 * 64; i += 256) {
        const int r = i >> 6, c = i & 63;
        QsT[c][r] = Qg[i];
    }

    float m_i[4], l_i[4], acc[4][4];
    #pragma unroll
    for (int i = 0; i < 4; i++) {
        m_i[i] = -1e30f;
        l_i[i] = 0.0f;
        #pragma unroll
        for (int j = 0; j < 4; j++) acc[i][j] = 0.0f;
    }

    const float scale = 0.125f; // HD^-0.5
    const int ntiles = qt + 1;

    for (int t = 0; t < ntiles; t++) {
        const int k0 = t * 64;
        __syncthreads();   // prior PV reads done (and Q load at t=0)
        for (int i = tid; i < 64 * 64; i += 256) {
            const int r = i >> 6, c = i & 63;
            const float kvl = Kg0[k0 * HDIM + i];
            KsT[c][r] = kvl;                      // transposed
            Vs[r][c]  = Vg0[k0 * HDIM + i];       // row-major
        }
        __syncthreads();

        // S = Q K^T : per d, one broadcast float4 (qv) + one spread float4 (kv)
        float s[4][4] = {};
        #pragma unroll 8
        for (int d = 0; d < 64; d++) {
            const float4 q4 = *(const float4*)&QsT[d][4 * ty];
            const float4 k4 = *(const float4*)&KsT[d][4 * tx];
            const float qv[4] = {q4.x, q4.y, q4.z, q4.w};
            const float kv[4] = {k4.x, k4.y, k4.z, k4.w};
            #pragma unroll
            for (int i = 0; i < 4; i++)
                #pragma unroll
                for (int j = 0; j < 4; j++)
                    s[i][j] += qv[i] * kv[j];
        }

        // scale + causal mask
        #pragma unroll
        for (int i = 0; i < 4; i++) {
            const int rg = q0 + 4 * ty + i;
            #pragma unroll
            for (int j = 0; j < 4; j++) {
                const int cg = k0 + 4 * tx + j;
                float val = s[i][j] * scale;
                if (cg > rg) val = -1e30f;
                s[i][j] = val;
            }
        }

        // online softmax (row reductions across 16-lane tx groups)
        #pragma unroll
        for (int i = 0; i < 4; i++) {
            float mx = fmaxf(fmaxf(s[i][0], s[i][1]), fmaxf(s[i][2], s[i][3]));
            #pragma unroll
            for (int off = 8; off >= 1; off >>= 1)
                mx = fmaxf(mx, __shfl_xor_sync(0xffffffffu, mx, off));
            const float mn = fmaxf(m_i[i], mx);
            const float corr = __expf(m_i[i] - mn);
            m_i[i] = mn;
            float rs = 0.0f;
            #pragma unroll
            for (int j = 0; j < 4; j++) {
                s[i][j] = __expf(s[i][j] - mn);
                rs += s[i][j];
            }
            #pragma unroll
            for (int off = 8; off >= 1; off >>= 1)
                rs += __shfl_xor_sync(0xffffffffu, rs, off);
            l_i[i] = l_i[i] * corr + rs;
            #pragma unroll
            for (int j = 0; j < 4; j++) acc[i][j] *= corr;
        }

        // write P (prior PV reads finished before this iteration's top sync)
        #pragma unroll
        for (int i = 0; i < 4; i++)
            #pragma unroll
            for (int j = 0; j < 4; j++)
                Ps[4 * ty + i][4 * tx + j] = s[i][j];
        __syncthreads();   // P visible

        // O += P V : pv broadcast scalars, vv one float4
        #pragma unroll 4
        for (int kk = 0; kk < 64; kk++) {
            float pv[4];
            #pragma unroll
            for (int i = 0; i < 4; i++) pv[i] = Ps[4 * ty + i][kk];
            const float4 v4 = *(const float4*)&Vs[kk][4 * tx];
            const float vv[4] = {v4.x, v4.y, v4.z, v4.w};
            #pragma unroll
            for (int i = 0; i < 4; i++)
                #pragma unroll
                for (int j = 0; j < 4; j++)
                    acc[i][j] += pv[i] * vv[j];
        }
    }

    // write out: g_attn[b][s][h*HD + d]
    #pragma unroll
    for (int i = 0; i < 4; i++) {
        const int rg = q0 + 4 * ty + i;
        const float inv_l = 1.0f / l_i[i];
        #pragma unroll
        for (int j = 0; j < 4; j++) {
            g_attn[((long)(b * SEQ + rg)) * HID + h * HDIM + 4 * tx + j] =
                acc[i][j] * inv_l;
        }
    }
}

// ---------------------------------------------------------------------------
// Stage 3: output projection  (byte-identical to the R8 passing version)
// ---------------------------------------------------------------------------
__global__ __launch_bounds__(256) void out_gemm(const float* __restrict__ W,
                                                const float* __restrict__ bias,
                                                float* __restrict__ Out)
{
    const int K = HID;
    const int N = HID;
    __shared__ float As[8][128];
    __shared__ float Bs[8][128];

    const int tid = threadIdx.x;
    const int m0 = blockIdx.y * 128;
    const int n0 = blockIdx.x * 128;

    const int arow = tid >> 1;
    const int acol = (tid & 1) * 4;
    const int brow = tid >> 5;
    const int bcol = (tid & 31) * 4;

    const float* Ap = g_attn + (long)(m0 + arow) * K + acol;
    const float* Bp = W + brow * N + n0 + bcol;

    float acc[8][8] = {};
    const int ty = tid >> 4, tx = tid & 15;

    float4 av = *(const float4*)(Ap);
    float4 bv = *(const float4*)(Bp);

    for (int k0 = 0; k0 < K; k0 += 8) {
        As[acol + 0][arow] = av.x;
        As[acol + 1][arow] = av.y;
        As[acol + 2][arow] = av.z;
        As[acol + 3][arow] = av.w;
        *(float4*)&Bs[brow][bcol] = bv;
        __syncthreads();

        if (k0 + 8 < K) {
            av = *(const float4*)(Ap + k0 + 8);
            bv = *(const float4*)(Bp + (long)(k0 + 8) * N);
        }

        #pragma unroll
        for (int kk = 0; kk < 8; kk++) {
            float4 a0 = *(const float4*)&As[kk][ty * 8];
            float4 a1 = *(const float4*)&As[kk][ty * 8 + 4];
            float4 b0 = *(const float4*)&Bs[kk][tx * 8];
            float4 b1 = *(const float4*)&Bs[kk][tx * 8 + 4];
            float a[8] = {a0.x,a0.y,a0.z,a0.w,a1.x,a1.y,a1.z,a1.w};
            float b[8] = {b0.x,b0.y,b0.z,b0.w,b1.x,b1.y,b1.z,b1.w};
            #pragma unroll
            for (int i = 0; i < 8; i++)
                #pragma unroll
                for (int j = 0; j < 8; j++)
                    acc[i][j] += a[i] * b[j];
        }
        __syncthreads();
    }

    #pragma unroll
    for (int i = 0; i < 8; i++) {
        const int m = m0 + ty * 8 + i;
        #pragma unroll
        for (int j = 0; j < 8; j++) {
            const int n = n0 + tx * 8 + j;
            Out[(long)m * N + n] = acc[i][j] + bias[n];
        }
    }
}

// ---------------------------------------------------------------------------
extern "C" void kernel_launch(void* const* d_in, const int* in_sizes, int n_in,
                              void* d_out, int out_size)
{
    const float* x     = (const float*)d_in[0];
    const float* w_qkv = (const float*)d_in[1];
    const float* b_qkv = (const float*)d_in[2];
    const float* w_out = (const float*)d_in[3];
    const float* b_out = (const float*)d_in[4];
    float* out = (float*)d_out;

    // Stage 1: QKV projection + head scatter
    qkv_gemm<<<dim3(3 * HID / 128, (BATCH * SEQ) / 128), 256>>>(x, w_qkv, b_qkv);

    // Stage 2: causal flash attention
    const int shmem = 4 * 64 * 68 * (int)sizeof(float);   // 69632 B
    cudaFuncSetAttribute(flash_attn,
                         cudaFuncAttributeMaxDynamicSharedMemorySize, shmem);
    flash_attn<<<dim3(SEQ / 64, NHEAD, BATCH), 256, shmem>>>();

    // Stage 3: output projection
    out_gemm<<<dim3(HID / 128, (BATCH * SEQ) / 128), 256>>>(w_out, b_out, out);
}

// round 11
// speedup vs baseline: 1.1143x; 1.0226x over previous
#include <cuda_runtime.h>

#define BATCH 4
#define SEQ   2048
#define HID   1024
#define NHEAD 16
#define HDIM  64

// Scratch (static device globals — allowed; no runtime allocation)
__device__ float g_q[BATCH*NHEAD*SEQ*HDIM];
__device__ float g_k[BATCH*NHEAD*SEQ*HDIM];
__device__ float g_v[BATCH*NHEAD*SEQ*HDIM];
__device__ float g_attn[BATCH*SEQ*HID];

// ---------------------------------------------------------------------------
// Stage 1: QKV GEMM  (byte-identical to the R8/R10 passing version)
// ---------------------------------------------------------------------------
__global__ __launch_bounds__(256) void qkv_gemm(const float* __restrict__ A,
                                                const float* __restrict__ W,
                                                const float* __restrict__ bias)
{
    const int K = HID;
    const int N = 3 * HID;
    __shared__ float As[8][128];
    __shared__ float Bs[8][128];

    const int tid = threadIdx.x;
    const int m0 = blockIdx.y * 128;
    const int n0 = blockIdx.x * 128;

    const int arow = tid >> 1;          // 0..127
    const int acol = (tid & 1) * 4;     // 0 or 4
    const int brow = tid >> 5;          // 0..7
    const int bcol = (tid & 31) * 4;    // 0..124

    const float* Ap = A + (m0 + arow) * K + acol;
    const float* Bp = W + brow * N + n0 + bcol;

    float acc[8][8] = {};
    const int ty = tid >> 4, tx = tid & 15;

    // stage tile 0
    float4 av = *(const float4*)(Ap);
    float4 bv = *(const float4*)(Bp);

    for (int k0 = 0; k0 < K; k0 += 8) {
        As[acol + 0][arow] = av.x;
        As[acol + 1][arow] = av.y;
        As[acol + 2][arow] = av.z;
        As[acol + 3][arow] = av.w;
        *(float4*)&Bs[brow][bcol] = bv;
        __syncthreads();

        if (k0 + 8 < K) {
            av = *(const float4*)(Ap + k0 + 8);
            bv = *(const float4*)(Bp + (long)(k0 + 8) * N);
        }

        #pragma unroll
        for (int kk = 0; kk < 8; kk++) {
            float4 a0 = *(const float4*)&As[kk][ty * 8];
            float4 a1 = *(const float4*)&As[kk][ty * 8 + 4];
            float4 b0 = *(const float4*)&Bs[kk][tx * 8];
            float4 b1 = *(const float4*)&Bs[kk][tx * 8 + 4];
            float a[8] = {a0.x,a0.y,a0.z,a0.w,a1.x,a1.y,a1.z,a1.w};
            float b[8] = {b0.x,b0.y,b0.z,b0.w,b1.x,b1.y,b1.z,b1.w};
            #pragma unroll
            for (int i = 0; i < 8; i++)
                #pragma unroll
                for (int j = 0; j < 8; j++)
                    acc[i][j] += a[i] * b[j];
        }
        __syncthreads();
    }

    #pragma unroll
    for (int i = 0; i < 8; i++) {
        const int m = m0 + ty * 8 + i;
        const int bb = m >> 11;          // / SEQ
        const int s  = m & 2047;
        #pragma unroll
        for (int j = 0; j < 8; j++) {
            const int n = n0 + tx * 8 + j;
            const float v = acc[i][j] + bias[n];
            const int which = n >> 10;
            const int rem = n & 1023;
            const int h = rem >> 6;
            const int d = rem & 63;
            const int idx = (((bb * NHEAD) + h) * SEQ + s) * HDIM + d;
            if (which == 0)      g_q[idx] = v;
            else if (which == 1) g_k[idx] = v;
            else                 g_v[idx] = v;
        }
    }
}

// ---------------------------------------------------------------------------
// Stage 2: causal flash attention, fp32, 128-query tiles, 8x4 per-thread.
// 256 threads = 16(ty) x 16(tx); thread owns q-rows 8ty..8ty+7 and
// k/d-cols 4tx..4tx+3. Q/K transposed in smem for LDS.128; V row-major;
// PV packed in kk-chunks of 4. P exchange is within 16-lane tx groups
// only => __syncwarp suffices. S computed in two 4-row halves to cap regs.
// Fully-masked halves (last diagonal tile only) write zero P rows (exact).
// smem: 64*132 + 2*64*68 + 128*68 floats = 103424 B.
// ---------------------------------------------------------------------------
__global__ __launch_bounds__(256, 2) void flash_attn()
{
    extern __shared__ float sm[];
    float (*QsT)[132] = (float(*)[132])sm;                          // [d][query]
    float (*KsT)[68]  = (float(*)[68])(sm + 64 * 132);              // [d][key]
    float (*Vs)[68]   = (float(*)[68])(sm + 64 * 132 + 64 * 68);    // [key][d]
    float (*Ps)[68]   = (float(*)[68])(sm + 64 * 132 + 2 * 64 * 68);// [query][key]

    const int b  = blockIdx.z;
    const int h  = blockIdx.y;
    const int qt = blockIdx.x;
    const int q0 = qt * 128;

    const float* Qg  = g_q + (((long)(b * NHEAD + h)) * SEQ + q0) * HDIM;
    const float* Kg0 = g_k + ((long)(b * NHEAD + h)) * SEQ * HDIM;
    const float* Vg0 = g_v + ((long)(b * NHEAD + h)) * SEQ * HDIM;

    const int tid = threadIdx.x;
    const int ty = tid >> 4, tx = tid & 15;
    const int rbase = 8 * ty;

    // load Q tile transposed: QsT[d][q] = Q[q][d]  (128 rows x 64 d)
    for (int i = tid; i < 128 * 64; i += 256) {
        const int r = i >> 6, c = i & 63;
        QsT[c][r] = Qg[i];
    }

    float m_i[8], l_i[8], acc[8][4];
    #pragma unroll
    for (int i = 0; i < 8; i++) {
        m_i[i] = -1e30f;
        l_i[i] = 0.0f;
        #pragma unroll
        for (int j = 0; j < 4; j++) acc[i][j] = 0.0f;
    }

    const float scale = 0.125f; // HD^-0.5
    const int ntiles = 2 * qt + 2;

    for (int t = 0; t < ntiles; t++) {
        const int k0 = t * 64;
        __syncthreads();   // prior tile's K/V reads done (and Q load at t=0)
        for (int i = tid; i < 64 * 64; i += 256) {
            const int r = i >> 6, c = i & 63;
            KsT[c][r] = Kg0[k0 * HDIM + i];   // [d][key]
            Vs[r][c]  = Vg0[k0 * HDIM + i];   // [key][d]
        }
        __syncthreads();

        // S + softmax in two 4-row halves (limits live registers)
        #pragma unroll
        for (int hf = 0; hf < 2; hf++) {
            const int rb = rbase + 4 * hf;
            const bool active = (q0 + rb + 3 >= k0);
            if (active) {
                float s[4][4] = {};
                #pragma unroll 4
                for (int d = 0; d < 64; d++) {
                    const float4 q4 = *(const float4*)&QsT[d][rb];
                    const float4 k4 = *(const float4*)&KsT[d][4 * tx];
                    const float qv[4] = {q4.x, q4.y, q4.z, q4.w};
                    const float kv[4] = {k4.x, k4.y, k4.z, k4.w};
                    #pragma unroll
                    for (int i = 0; i < 4; i++)
                        #pragma unroll
                        for (int j = 0; j < 4; j++)
                            s[i][j] += qv[i] * kv[j];
                }
                #pragma unroll
                for (int i = 0; i < 4; i++) {
                    const int rg = q0 + rb + i;
                    #pragma unroll
                    for (int j = 0; j < 4; j++) {
                        const int cg = k0 + 4 * tx + j;
                        float val = s[i][j] * scale;
                        if (cg > rg) val = -1e30f;
                        s[i][j] = val;
                    }
                }
                #pragma unroll
                for (int i = 0; i < 4; i++) {
                    const int ii = 4 * hf + i;
                    float mx = fmaxf(fmaxf(s[i][0], s[i][1]), fmaxf(s[i][2], s[i][3]));
                    #pragma unroll
                    for (int off = 8; off >= 1; off >>= 1)
                        mx = fmaxf(mx, __shfl_xor_sync(0xffffffffu, mx, off));
                    const float mn = fmaxf(m_i[ii], mx);
                    const float corr = __expf(m_i[ii] - mn);
                    m_i[ii] = mn;
                    float rs = 0.0f;
                    #pragma unroll
                    for (int j = 0; j < 4; j++) {
                        s[i][j] = __expf(s[i][j] - mn);
                        rs += s[i][j];
                    }
                    #pragma unroll
                    for (int off = 8; off >= 1; off >>= 1)
                        rs += __shfl_xor_sync(0xffffffffu, rs, off);
                    l_i[ii] = l_i[ii] * corr + rs;
                    #pragma unroll
                    for (int j = 0; j < 4; j++) acc[ii][j] *= corr;
                }
                #pragma unroll
                for (int i = 0; i < 4; i++)
                    #pragma unroll
                    for (int j = 0; j < 4; j++)
                        Ps[rb + i][4 * tx + j] = s[i][j];
            } else {
                // fully masked half: P rows are exactly zero
                #pragma unroll
                for (int i = 0; i < 4; i++)
                    #pragma unroll
                    for (int j = 0; j < 4; j++)
                        Ps[rb + i][4 * tx + j] = 0.0f;
            }
        }
        __syncwarp();   // P rows exchanged only within the 16-lane tx group

        // O += P V : kk chunks of 4 (pv and vv both LDS.128)
        #pragma unroll 2
        for (int kk = 0; kk < 64; kk += 4) {
            float4 pv4[8];
            #pragma unroll
            for (int i = 0; i < 8; i++)
                pv4[i] = *(const float4*)&Ps[rbase + i][kk];
            float4 vv[4];
            #pragma unroll
            for (int c = 0; c < 4; c++)
                vv[c] = *(const float4*)&Vs[kk + c][4 * tx];
            #pragma unroll
            for (int i = 0; i < 8; i++) {
                const float pv[4] = {pv4[i].x, pv4[i].y, pv4[i].z, pv4[i].w};
                #pragma unroll
                for (int c = 0; c < 4; c++) {   // kk-sequential: same order as before
                    acc[i][0] += pv[c] * vv[c].x;
                    acc[i][1] += pv[c] * vv[c].y;
                    acc[i][2] += pv[c] * vv[c].z;
                    acc[i][3] += pv[c] * vv[c].w;
                }
            }
        }
        __syncwarp();   // own P rows fully consumed before next overwrite
    }

    // write out: g_attn[b][s][h*HD + d]
    #pragma unroll
    for (int i = 0; i < 8; i++) {
        const int rg = q0 + rbase + i;
        const float inv_l = 1.0f / l_i[i];
        #pragma unroll
        for (int j = 0; j < 4; j++) {
            g_attn[((long)(b * SEQ + rg)) * HID + h * HDIM + 4 * tx + j] =
                acc[i][j] * inv_l;
        }
    }
}

// ---------------------------------------------------------------------------
// Stage 3: output projection  (byte-identical to the R8/R10 passing version)
// ---------------------------------------------------------------------------
__global__ __launch_bounds__(256) void out_gemm(const float* __restrict__ W,
                                                const float* __restrict__ bias,
                                                float* __restrict__ Out)
{
    const int K = HID;
    const int N = HID;
    __shared__ float As[8][128];
    __shared__ float Bs[8][128];

    const int tid = threadIdx.x;
    const int m0 = blockIdx.y * 128;
    const int n0 = blockIdx.x * 128;

    const int arow = tid >> 1;
    const int acol = (tid & 1) * 4;
    const int brow = tid >> 5;
    const int bcol = (tid & 31) * 4;

    const float* Ap = g_attn + (long)(m0 + arow) * K + acol;
    const float* Bp = W + brow * N + n0 + bcol;

    float acc[8][8] = {};
    const int ty = tid >> 4, tx = tid & 15;

    float4 av = *(const float4*)(Ap);
    float4 bv = *(const float4*)(Bp);

    for (int k0 = 0; k0 < K; k0 += 8) {
        As[acol + 0][arow] = av.x;
        As[acol + 1][arow] = av.y;
        As[acol + 2][arow] = av.z;
        As[acol + 3][arow] = av.w;
        *(float4*)&Bs[brow][bcol] = bv;
        __syncthreads();

        if (k0 + 8 < K) {
            av = *(const float4*)(Ap + k0 + 8);
            bv = *(const float4*)(Bp + (long)(k0 + 8) * N);
        }

        #pragma unroll
        for (int kk = 0; kk < 8; kk++) {
            float4 a0 = *(const float4*)&As[kk][ty * 8];
            float4 a1 = *(const float4*)&As[kk][ty * 8 + 4];
            float4 b0 = *(const float4*)&Bs[kk][tx * 8];
            float4 b1 = *(const float4*)&Bs[kk][tx * 8 + 4];
            float a[8] = {a0.x,a0.y,a0.z,a0.w,a1.x,a1.y,a1.z,a1.w};
            float b[8] = {b0.x,b0.y,b0.z,b0.w,b1.x,b1.y,b1.z,b1.w};
            #pragma unroll
            for (int i = 0; i < 8; i++)
                #pragma unroll
                for (int j = 0; j < 8; j++)
                    acc[i][j] += a[i] * b[j];
        }
        __syncthreads();
    }

    #pragma unroll
    for (int i = 0; i < 8; i++) {
        const int m = m0 + ty * 8 + i;
        #pragma unroll
        for (int j = 0; j < 8; j++) {
            const int n = n0 + tx * 8 + j;
            Out[(long)m * N + n] = acc[i][j] + bias[n];
        }
    }
}

// ---------------------------------------------------------------------------
extern "C" void kernel_launch(void* const* d_in, const int* in_sizes, int n_in,
                              void* d_out, int out_size)
{
    const float* x     = (const float*)d_in[0];
    const float* w_qkv = (const float*)d_in[1];
    const float* b_qkv = (const float*)d_in[2];
    const float* w_out = (const float*)d_in[3];
    const float* b_out = (const float*)d_in[4];
    float* out = (float*)d_out;

    // Stage 1: QKV projection + head scatter
    qkv_gemm<<<dim3(3 * HID / 128, (BATCH * SEQ) / 128), 256>>>(x, w_qkv, b_qkv);

    // Stage 2: causal flash attention (128-query tiles)
    const int shmem = (64 * 132 + 2 * 64 * 68 + 128 * 68) * (int)sizeof(float);
    cudaFuncSetAttribute(flash_attn,
                         cudaFuncAttributeMaxDynamicSharedMemorySize, shmem);
    flash_attn<<<dim3(SEQ / 128, NHEAD, BATCH), 256, shmem>>>();

    // Stage 3: output projection
    out_gemm<<<dim3(HID / 128, (BATCH * SEQ) / 128), 256>>>(w_out, b_out, out);
}